// round 1
// baseline (speedup 1.0000x reference)
#include <cuda_runtime.h>
#include <math.h>

#define Bb      64
#define Tt      128
#define Dd      768
#define Hh      256
#define NSPANS  8256
#define KTOP    256
#define XST     68          // padded SMEM stride (16B-aligned float4, conflict-free)

// ---------------- device scratch (no allocation allowed) ----------------
__device__ float g_A[Bb*Tt*Hh];
__device__ float g_E[Bb*Tt*Hh];
__device__ float g_scores[Bb*NSPANS];
__device__ float g_inj[Bb*Hh];
__device__ int   g_topidx[Bb*KTOP];
__device__ float g_topscore[Bb*KTOP];
__device__ int   g_sarr[NSPANS];
__device__ int   g_earr[NSPANS];

// ---------------- span index decode (row-major triu) ----------------
__global__ void build_span_idx_kernel() {
    int n = blockIdx.x * blockDim.x + threadIdx.x;
    if (n >= NSPANS) return;
    int s = 0, off = 0;
    while (n >= off + (Tt - s)) { off += (Tt - s); s++; }
    g_sarr[n] = s;
    g_earr[n] = s + (n - off);
}

// ---------------- start/end projections: X[8192,768] @ W[768,256] + b ----------------
__global__ void proj_kernel(const float* __restrict__ X,
                            const float* __restrict__ Wst, const float* __restrict__ bst,
                            const float* __restrict__ Wen, const float* __restrict__ ben) {
    const float* W    = blockIdx.z ? Wen : Wst;
    const float* bias = blockIdx.z ? ben : bst;
    float*       Out  = blockIdx.z ? g_E : g_A;

    __shared__ float xs[32 * XST];
    __shared__ float wsm[32 * XST];

    const int row0 = blockIdx.y * 64;
    const int col0 = blockIdx.x * 64;
    const int tid  = threadIdx.x;
    const int tx   = tid & 15, ty = tid >> 4;

    float c[4][4] = {};

    for (int k0 = 0; k0 < Dd; k0 += 32) {
        __syncthreads();
        #pragma unroll
        for (int idx = tid; idx < 64 * 32; idx += 256) {
            int r = idx >> 5, k = idx & 31;
            xs[k * XST + r] = X[(row0 + r) * Dd + k0 + k];
        }
        #pragma unroll
        for (int idx = tid; idx < 32 * 64; idx += 256) {
            int k = idx >> 6, cc = idx & 63;
            wsm[k * XST + cc] = W[(k0 + k) * Hh + col0 + cc];
        }
        __syncthreads();
        #pragma unroll 8
        for (int k = 0; k < 32; k++) {
            const float4 a = *(const float4*)(xs  + k * XST + (ty << 2));
            const float4 w = *(const float4*)(wsm + k * XST + (tx << 2));
            float av[4] = {a.x, a.y, a.z, a.w};
            float wv[4] = {w.x, w.y, w.z, w.w};
            #pragma unroll
            for (int i = 0; i < 4; i++)
                #pragma unroll
                for (int j = 0; j < 4; j++)
                    c[i][j] = fmaf(av[i], wv[j], c[i][j]);
        }
    }

    #pragma unroll
    for (int i = 0; i < 4; i++) {
        int row = row0 + (ty << 2) + i;
        #pragma unroll
        for (int j = 0; j < 4; j++) {
            int col = col0 + (tx << 2) + j;
            Out[row * Hh + col] = c[i][j] + bias[col];
        }
    }
}

// ---------------- injection projection: [64,128] @ [128,256] + b ----------------
__global__ void inj_kernel(const float* __restrict__ tie,
                           const float* __restrict__ Winj, const float* __restrict__ binj) {
    int b = blockIdx.x;
    int j = threadIdx.x;                 // 256 threads = H
    __shared__ float t[128];
    if (j < 128) t[j] = tie[b * 128 + j];
    __syncthreads();
    float acc = binj[j];
    #pragma unroll 8
    for (int k = 0; k < 128; k++) acc = fmaf(t[k], Winj[k * Hh + j], acc);
    g_inj[b * Hh + j] = acc;
}

// ---------------- fused span scorer: score = relu(relu(A_s+E_e)@W1+b1)@W2 + b2 ----------------
// grid (129, 64); block 256; dynamic smem 139776B
__global__ void scorer_kernel(const float* __restrict__ Ws1, const float* __restrict__ bs1,
                              const float* __restrict__ Ws2, const float* __restrict__ bs2) {
    extern __shared__ float sm[];
    float* xs   = sm;                       // 256*68
    float* ws   = xs + 256 * XST;           // 256*64
    float* bs1c = ws + 256 * 64;            // 64
    float* w2c  = bs1c + 64;                // 64
    float* red  = w2c + 64;                 // 64*16
    __shared__ int sS[64], sE[64];

    const int b   = blockIdx.y;
    const int n0  = blockIdx.x * 64;
    const int tid = threadIdx.x;
    const int tx  = tid & 15, ty = tid >> 4;

    if (tid < 64) { sS[tid] = g_sarr[n0 + tid]; sE[tid] = g_earr[n0 + tid]; }
    __syncthreads();

    const float* Ab = g_A + b * Tt * Hh;
    const float* Eb = g_E + b * Tt * Hh;
    // xs[k][r] = relu(A[s_r][k] + E[e_r][k]), k = tid (H == blockDim)
    for (int r = 0; r < 64; r++) {
        float v = Ab[sS[r] * Hh + tid] + Eb[sE[r] * Hh + tid];
        xs[tid * XST + r] = v > 0.f ? v : 0.f;
    }

    float scacc[4] = {0.f, 0.f, 0.f, 0.f};

    for (int jb = 0; jb < 4; jb++) {
        const int jbase = jb * 64;
        __syncthreads();
        #pragma unroll
        for (int idx = tid; idx < 256 * 64; idx += 256) {
            int k = idx >> 6, j = idx & 63;
            ws[idx] = Ws1[k * Hh + jbase + j];
        }
        if (tid < 64) { bs1c[tid] = bs1[jbase + tid]; w2c[tid] = Ws2[jbase + tid]; }
        __syncthreads();

        float c[4][4] = {};
        #pragma unroll 8
        for (int k = 0; k < Hh; k++) {
            const float4 a = *(const float4*)(xs + k * XST + (ty << 2));
            const float4 w = *(const float4*)(ws + (k << 6) + (tx << 2));
            float av[4] = {a.x, a.y, a.z, a.w};
            float wv[4] = {w.x, w.y, w.z, w.w};
            #pragma unroll
            for (int i = 0; i < 4; i++)
                #pragma unroll
                for (int j = 0; j < 4; j++)
                    c[i][j] = fmaf(av[i], wv[j], c[i][j]);
        }
        #pragma unroll
        for (int i = 0; i < 4; i++)
            #pragma unroll
            for (int j = 0; j < 4; j++) {
                float h = c[i][j] + bs1c[(tx << 2) + j];
                if (h > 0.f) scacc[i] = fmaf(h, w2c[(tx << 2) + j], scacc[i]);
            }
    }

    __syncthreads();
    #pragma unroll
    for (int i = 0; i < 4; i++) red[((ty << 2) + i) * 16 + tx] = scacc[i];
    __syncthreads();
    if (tid < 64) {
        float ssum = bs2[0];
        #pragma unroll
        for (int t = 0; t < 16; t++) ssum += red[tid * 16 + t];
        g_scores[b * NSPANS + n0 + tid] = ssum;
    }
}

// ---------------- per-batch radix top-k (k=256, stable ties, ascending index output) ----------------
__global__ void topk_kernel(const int* __restrict__ mask) {
    const int b   = blockIdx.x;
    const int tid = threadIdx.x;       // 256
    __shared__ unsigned keys[NSPANS];
    __shared__ int hist[256];
    __shared__ unsigned sh_prefix;
    __shared__ int sh_kk;

    const int* mb = mask + b * Tt;
    for (int i = tid; i < NSPANS; i += 256) {
        int s = g_sarr[i], e = g_earr[i];
        float v = (mb[s] != 0 && mb[e] != 0) ? g_scores[b * NSPANS + i]
                                             : __int_as_float(0xff800000); // -inf
        unsigned u = __float_as_uint(v);
        keys[i] = (u & 0x80000000u) ? ~u : (u | 0x80000000u);   // order-preserving
    }

    unsigned prefix = 0;
    int kk = KTOP;
    for (int level = 3; level >= 0; level--) {
        hist[tid] = 0;
        __syncthreads();
        const unsigned himask = (level == 3) ? 0u : (0xFFFFFFFFu << ((level + 1) * 8));
        for (int i = tid; i < NSPANS; i += 256) {
            unsigned kv = keys[i];
            if ((kv & himask) == (prefix & himask))
                atomicAdd(&hist[(kv >> (level * 8)) & 255], 1);
        }
        __syncthreads();
        if (tid == 0) {
            int cum = 0, chosen = 0, kknew = kk;
            for (int t = 255; t >= 0; t--) {
                int c = hist[t];
                if (cum + c >= kk) { chosen = t; kknew = kk - cum; break; }
                cum += c;
            }
            sh_prefix = prefix | ((unsigned)chosen << (level * 8));
            sh_kk = kknew;
        }
        __syncthreads();
        prefix = sh_prefix;
        kk = sh_kk;
        __syncthreads();
    }

    if (tid == 0) {
        const unsigned Kstar = prefix;
        int eqneed = kk, pos = 0;
        for (int i = 0; i < NSPANS && pos < KTOP; i++) {
            unsigned kv = keys[i];
            bool take = (kv > Kstar);
            if (!take && kv == Kstar && eqneed > 0) { take = true; eqneed--; }
            if (take) {
                unsigned u = (kv & 0x80000000u) ? (kv & 0x7FFFFFFFu) : ~kv;
                g_topidx[b * KTOP + pos]   = i;
                g_topscore[b * KTOP + pos] = __uint_as_float(u);
                pos++;
            }
        }
    }
}

// ---------------- fused head: sigmoid(relu(inj + th@Wsec+bsec)@Wpred + bpred + score) * mask ----------------
// grid (4, 64); block 256; dynamic smem 139776B
__global__ void head_kernel(const float* __restrict__ Wsec, const float* __restrict__ bsec,
                            const float* __restrict__ Wpred, const float* __restrict__ bpred,
                            const int* __restrict__ mask, float* __restrict__ out) {
    extern __shared__ float sm[];
    float* xs  = sm;                        // 256*68
    float* ws  = xs + 256 * XST;            // 256*64
    float* bc  = ws + 256 * 64;             // 64 (bsec + inj)
    float* wpc = bc + 64;                   // 64
    float* red = wpc + 64;                  // 64*16
    __shared__ int sS[64], sE[64];
    __shared__ float sMask[64], sScore[64];

    const int b   = blockIdx.y;
    const int k0  = blockIdx.x * 64;
    const int tid = threadIdx.x;
    const int tx  = tid & 15, ty = tid >> 4;

    if (tid < 64) {
        int n = g_topidx[b * KTOP + k0 + tid];
        int s = g_sarr[n], e = g_earr[n];
        sS[tid] = s; sE[tid] = e;
        sMask[tid] = (mask[b * Tt + s] != 0 && mask[b * Tt + e] != 0) ? 1.f : 0.f;
        float sc = g_topscore[b * KTOP + k0 + tid];
        sScore[tid] = isinf(sc) ? -1.f : sc;
    }
    __syncthreads();

    const float* Ab = g_A + b * Tt * Hh;
    const float* Eb = g_E + b * Tt * Hh;
    for (int r = 0; r < 64; r++)
        xs[tid * XST + r] = Ab[sS[r] * Hh + tid] + Eb[sE[r] * Hh + tid];  // no relu here

    float scacc[4] = {0.f, 0.f, 0.f, 0.f};

    for (int jb = 0; jb < 4; jb++) {
        const int jbase = jb * 64;
        __syncthreads();
        #pragma unroll
        for (int idx = tid; idx < 256 * 64; idx += 256) {
            int k = idx >> 6, j = idx & 63;
            ws[idx] = Wsec[k * Hh + jbase + j];
        }
        if (tid < 64) {
            bc[tid]  = bsec[jbase + tid] + g_inj[b * Hh + jbase + tid];
            wpc[tid] = Wpred[jbase + tid];
        }
        __syncthreads();

        float c[4][4] = {};
        #pragma unroll 8
        for (int k = 0; k < Hh; k++) {
            const float4 a = *(const float4*)(xs + k * XST + (ty << 2));
            const float4 w = *(const float4*)(ws + (k << 6) + (tx << 2));
            float av[4] = {a.x, a.y, a.z, a.w};
            float wv[4] = {w.x, w.y, w.z, w.w};
            #pragma unroll
            for (int i = 0; i < 4; i++)
                #pragma unroll
                for (int j = 0; j < 4; j++)
                    c[i][j] = fmaf(av[i], wv[j], c[i][j]);
        }
        #pragma unroll
        for (int i = 0; i < 4; i++)
            #pragma unroll
            for (int j = 0; j < 4; j++) {
                float h = c[i][j] + bc[(tx << 2) + j];
                if (h > 0.f) scacc[i] = fmaf(h, wpc[(tx << 2) + j], scacc[i]);
            }
    }

    __syncthreads();
    #pragma unroll
    for (int i = 0; i < 4; i++) red[((ty << 2) + i) * 16 + tx] = scacc[i];
    __syncthreads();
    if (tid < 64) {
        float ssum = bpred[0] + sScore[tid];
        #pragma unroll
        for (int t = 0; t < 16; t++) ssum += red[tid * 16 + t];
        float p = 1.f / (1.f + expf(-ssum));
        out[b * KTOP + k0 + tid] = p * sMask[tid];
    }
}

// ---------------- launch ----------------
static const int SMEM_BYTES = (256 * XST + 256 * 64 + 64 + 64 + 64 * 16) * 4; // 139776

extern "C" void kernel_launch(void* const* d_in, const int* in_sizes, int n_in,
                              void* d_out, int out_size) {
    const float* inputs   = (const float*)d_in[0];
    const int*   in_mask  = (const int*)  d_in[1];
    const float* tie      = (const float*)d_in[2];
    const float* W_start  = (const float*)d_in[3];
    const float* b_start  = (const float*)d_in[4];
    const float* W_end    = (const float*)d_in[5];
    const float* b_end    = (const float*)d_in[6];
    const float* W_s1     = (const float*)d_in[7];
    const float* b_s1     = (const float*)d_in[8];
    const float* W_s2     = (const float*)d_in[9];
    const float* b_s2     = (const float*)d_in[10];
    const float* W_inj    = (const float*)d_in[11];
    const float* b_inj    = (const float*)d_in[12];
    const float* W_sec    = (const float*)d_in[13];
    const float* b_sec    = (const float*)d_in[14];
    const float* W_pred   = (const float*)d_in[15];
    const float* b_pred   = (const float*)d_in[16];
    float* out = (float*)d_out;

    cudaFuncSetAttribute(scorer_kernel, cudaFuncAttributeMaxDynamicSharedMemorySize, SMEM_BYTES);
    cudaFuncSetAttribute(head_kernel,   cudaFuncAttributeMaxDynamicSharedMemorySize, SMEM_BYTES);

    build_span_idx_kernel<<<(NSPANS + 255) / 256, 256>>>();
    proj_kernel<<<dim3(Hh / 64, (Bb * Tt) / 64, 2), 256>>>(inputs, W_start, b_start, W_end, b_end);
    inj_kernel<<<Bb, 256>>>(tie, W_inj, b_inj);
    scorer_kernel<<<dim3(NSPANS / 64, Bb), 256, SMEM_BYTES>>>(W_s1, b_s1, W_s2, b_s2);
    topk_kernel<<<Bb, 256>>>(in_mask);
    head_kernel<<<dim3(KTOP / 64, Bb), 256, SMEM_BYTES>>>(W_sec, b_sec, W_pred, b_pred, in_mask, out);
}

// round 2
// speedup vs baseline: 1.4322x; 1.4322x over previous
#include <cuda_runtime.h>
#include <math.h>

#define Bb      64
#define Tt      128
#define Dd      768
#define Hh      256
#define NSPANS  8256
#define KTOP    256
#define XST     68          // padded SMEM stride for xs (16B-aligned, conflict-tamed)

typedef unsigned long long u64;

// ---------------- packed fp32x2 helpers (sm_103a FFMA2 path) ----------------
__device__ __forceinline__ u64 dup2(float a) {
    u64 r;
    asm("mov.b64 %0, {%1, %2};" : "=l"(r) : "f"(a), "f"(a));
    return r;
}
__device__ __forceinline__ void fma2(u64& acc, u64 a, u64 b) {
    asm("fma.rn.f32x2 %0, %1, %2, %0;" : "+l"(acc) : "l"(a), "l"(b));
}
__device__ __forceinline__ void unpack2(float& lo, float& hi, u64 v) {
    asm("mov.b64 {%0, %1}, %2;" : "=f"(lo), "=f"(hi) : "l"(v));
}
__device__ __forceinline__ void lds_pair(u64& x, u64& y, const float* p) {
    unsigned addr = (unsigned)__cvta_generic_to_shared(p);
    asm volatile("ld.shared.v2.u64 {%0, %1}, [%2];" : "=l"(x), "=l"(y) : "r"(addr));
}

// ---------------- device scratch (no allocation allowed) ----------------
__device__ float g_A[Bb*Tt*Hh];
__device__ float g_E[Bb*Tt*Hh];
__device__ float g_scores[Bb*NSPANS];
__device__ float g_inj[Bb*Hh];
__device__ int   g_topidx[Bb*KTOP];
__device__ float g_topscore[Bb*KTOP];
__device__ int   g_sarr[NSPANS];
__device__ int   g_earr[NSPANS];

// ---------------- span index decode (row-major triu) ----------------
__global__ void build_span_idx_kernel() {
    int n = blockIdx.x * blockDim.x + threadIdx.x;
    if (n >= NSPANS) return;
    int s = 0, off = 0;
    while (n >= off + (Tt - s)) { off += (Tt - s); s++; }
    g_sarr[n] = s;
    g_earr[n] = s + (n - off);
}

// ---------------- start/end projections: X[8192,768] @ W[768,256] + b ----------------
__global__ __launch_bounds__(256)
void proj_kernel(const float* __restrict__ X,
                 const float* __restrict__ Wst, const float* __restrict__ bst,
                 const float* __restrict__ Wen, const float* __restrict__ ben) {
    const float* W    = blockIdx.z ? Wen : Wst;
    const float* bias = blockIdx.z ? ben : bst;
    float*       Out  = blockIdx.z ? g_E : g_A;

    __shared__ float xs[32 * XST];
    __shared__ float wsm[32 * XST];

    const int row0 = blockIdx.y * 64;
    const int col0 = blockIdx.x * 64;
    const int tid  = threadIdx.x;
    const int tx   = tid & 15, ty = tid >> 4;

    u64 acc[4][2] = {};   // rows (ty*4+i) x col-pairs (tx*4 + 2p)

    for (int k0 = 0; k0 < Dd; k0 += 32) {
        __syncthreads();
        #pragma unroll
        for (int idx = tid; idx < 64 * 32; idx += 256) {
            int r = idx >> 5, k = idx & 31;
            xs[k * XST + r] = X[(row0 + r) * Dd + k0 + k];
        }
        #pragma unroll
        for (int idx = tid; idx < 32 * 64; idx += 256) {
            int k = idx >> 6, cc = idx & 63;
            wsm[k * XST + cc] = W[(k0 + k) * Hh + col0 + cc];
        }
        __syncthreads();
        #pragma unroll 8
        for (int k = 0; k < 32; k++) {
            const float4 a = *(const float4*)(xs + k * XST + (ty << 2));
            u64 w0, w1;
            lds_pair(w0, w1, wsm + k * XST + (tx << 2));
            u64 d0 = dup2(a.x), d1 = dup2(a.y), d2 = dup2(a.z), d3 = dup2(a.w);
            fma2(acc[0][0], d0, w0); fma2(acc[0][1], d0, w1);
            fma2(acc[1][0], d1, w0); fma2(acc[1][1], d1, w1);
            fma2(acc[2][0], d2, w0); fma2(acc[2][1], d2, w1);
            fma2(acc[3][0], d3, w0); fma2(acc[3][1], d3, w1);
        }
    }

    #pragma unroll
    for (int i = 0; i < 4; i++) {
        int row = row0 + (ty << 2) + i;
        #pragma unroll
        for (int p = 0; p < 2; p++) {
            float lo, hi;
            unpack2(lo, hi, acc[i][p]);
            int col = col0 + (tx << 2) + 2 * p;
            Out[row * Hh + col]     = lo + bias[col];
            Out[row * Hh + col + 1] = hi + bias[col + 1];
        }
    }
}

// ---------------- injection projection: [64,128] @ [128,256] + b ----------------
__global__ void inj_kernel(const float* __restrict__ tie,
                           const float* __restrict__ Winj, const float* __restrict__ binj) {
    int b = blockIdx.x;
    int j = threadIdx.x;
    __shared__ float t[128];
    if (j < 128) t[j] = tie[b * 128 + j];
    __syncthreads();
    float acc = binj[j];
    #pragma unroll 8
    for (int k = 0; k < 128; k++) acc = fmaf(t[k], Winj[k * Hh + j], acc);
    g_inj[b * Hh + j] = acc;
}

// ============ fused 64-span x 256-col GEMM body (FFMA2), shared by scorer & head ============
// xs: [256][XST] activations (k-major), ws: [256][128] weight stage
// per-thread tile: rows = ty*4..+3, cols = {tx*4..+3} and {64+tx*4..+3} within stage

#define GEMM_SMEM_FLOATS (256*XST + 256*128 + 128 + 128 + 64*16)
static const int SMEM_BYTES = GEMM_SMEM_FLOATS * 4;  // 205,824 B

// ---------------- fused span scorer ----------------
__global__ __launch_bounds__(256, 1)
void scorer_kernel(const float* __restrict__ Ws1, const float* __restrict__ bs1,
                   const float* __restrict__ Ws2, const float* __restrict__ bs2) {
    extern __shared__ float sm[];
    float* xs   = sm;                       // 256*68
    float* ws   = xs + 256 * XST;           // 256*128
    float* bs1c = ws + 256 * 128;           // 128
    float* w2c  = bs1c + 128;               // 128
    float* red  = w2c + 128;                // 64*16
    __shared__ int sS[64], sE[64];

    const int b   = blockIdx.y;
    const int n0  = blockIdx.x * 64;
    const int tid = threadIdx.x;
    const int tx  = tid & 15, ty = tid >> 4;

    if (tid < 64) { sS[tid] = g_sarr[n0 + tid]; sE[tid] = g_earr[n0 + tid]; }
    __syncthreads();

    const float* Ab = g_A + b * Tt * Hh;
    const float* Eb = g_E + b * Tt * Hh;
    for (int r = 0; r < 64; r++) {
        float v = Ab[sS[r] * Hh + tid] + Eb[sE[r] * Hh + tid];
        xs[tid * XST + r] = v > 0.f ? v : 0.f;
    }

    float scacc[4] = {0.f, 0.f, 0.f, 0.f};

    #pragma unroll 1
    for (int jb = 0; jb < 2; jb++) {
        const int jbase = jb * 128;
        __syncthreads();
        // stage 256x128 weight chunk, float4 vectorized
        #pragma unroll
        for (int idx = tid; idx < 8192; idx += 256) {
            int k = idx >> 5, c4 = idx & 31;
            ((float4*)ws)[idx] = ((const float4*)(Ws1 + k * Hh + jbase))[c4];
        }
        if (tid < 128) { bs1c[tid] = bs1[jbase + tid]; w2c[tid] = Ws2[jbase + tid]; }
        __syncthreads();

        u64 acc[4][4] = {};
        const float* xp = xs + (ty << 2);
        const float* wl = ws + (tx << 2);
        const float* wh = wl + 64;
        #pragma unroll 4
        for (int k = 0; k < Hh; k++) {
            const float4 a = *(const float4*)(xp + k * XST);
            u64 w0, w1, w2, w3;
            lds_pair(w0, w1, wl + (k << 7));
            lds_pair(w2, w3, wh + (k << 7));
            u64 d0 = dup2(a.x), d1 = dup2(a.y), d2 = dup2(a.z), d3 = dup2(a.w);
            fma2(acc[0][0], d0, w0); fma2(acc[0][1], d0, w1);
            fma2(acc[0][2], d0, w2); fma2(acc[0][3], d0, w3);
            fma2(acc[1][0], d1, w0); fma2(acc[1][1], d1, w1);
            fma2(acc[1][2], d1, w2); fma2(acc[1][3], d1, w3);
            fma2(acc[2][0], d2, w0); fma2(acc[2][1], d2, w1);
            fma2(acc[2][2], d2, w2); fma2(acc[2][3], d2, w3);
            fma2(acc[3][0], d3, w0); fma2(acc[3][1], d3, w1);
            fma2(acc[3][2], d3, w2); fma2(acc[3][3], d3, w3);
        }
        // layer-2 epilogue for this stage
        #pragma unroll
        for (int i = 0; i < 4; i++) {
            #pragma unroll
            for (int p = 0; p < 4; p++) {
                float lo, hi;
                unpack2(lo, hi, acc[i][p]);
                int cb = (p < 2) ? ((tx << 2) + 2 * p) : (64 + (tx << 2) + 2 * (p - 2));
                float h0 = lo + bs1c[cb];
                if (h0 > 0.f) scacc[i] = fmaf(h0, w2c[cb], scacc[i]);
                float h1 = hi + bs1c[cb + 1];
                if (h1 > 0.f) scacc[i] = fmaf(h1, w2c[cb + 1], scacc[i]);
            }
        }
    }

    __syncthreads();
    #pragma unroll
    for (int i = 0; i < 4; i++) red[((ty << 2) + i) * 16 + tx] = scacc[i];
    __syncthreads();
    if (tid < 64) {
        float ssum = bs2[0];
        #pragma unroll
        for (int t = 0; t < 16; t++) ssum += red[tid * 16 + t];
        g_scores[b * NSPANS + n0 + tid] = ssum;
    }
}

// ---------------- per-batch radix top-k (k=256, stable ties, ascending index output) ----------------
__global__ void topk_kernel(const int* __restrict__ mask) {
    const int b   = blockIdx.x;
    const int tid = threadIdx.x;
    __shared__ unsigned keys[NSPANS];
    __shared__ int hist[256];
    __shared__ unsigned sh_prefix;
    __shared__ int sh_kk;

    const int* mb = mask + b * Tt;
    for (int i = tid; i < NSPANS; i += 256) {
        int s = g_sarr[i], e = g_earr[i];
        float v = (mb[s] != 0 && mb[e] != 0) ? g_scores[b * NSPANS + i]
                                             : __int_as_float(0xff800000);
        unsigned u = __float_as_uint(v);
        keys[i] = (u & 0x80000000u) ? ~u : (u | 0x80000000u);
    }

    unsigned prefix = 0;
    int kk = KTOP;
    for (int level = 3; level >= 0; level--) {
        hist[tid] = 0;
        __syncthreads();
        const unsigned himask = (level == 3) ? 0u : (0xFFFFFFFFu << ((level + 1) * 8));
        for (int i = tid; i < NSPANS; i += 256) {
            unsigned kv = keys[i];
            if ((kv & himask) == (prefix & himask))
                atomicAdd(&hist[(kv >> (level * 8)) & 255], 1);
        }
        __syncthreads();
        if (tid == 0) {
            int cum = 0, chosen = 0, kknew = kk;
            for (int t = 255; t >= 0; t--) {
                int c = hist[t];
                if (cum + c >= kk) { chosen = t; kknew = kk - cum; break; }
                cum += c;
            }
            sh_prefix = prefix | ((unsigned)chosen << (level * 8));
            sh_kk = kknew;
        }
        __syncthreads();
        prefix = sh_prefix;
        kk = sh_kk;
        __syncthreads();
    }

    if (tid == 0) {
        const unsigned Kstar = prefix;
        int eqneed = kk, pos = 0;
        for (int i = 0; i < NSPANS && pos < KTOP; i++) {
            unsigned kv = keys[i];
            bool take = (kv > Kstar);
            if (!take && kv == Kstar && eqneed > 0) { take = true; eqneed--; }
            if (take) {
                unsigned u = (kv & 0x80000000u) ? (kv & 0x7FFFFFFFu) : ~kv;
                g_topidx[b * KTOP + pos]   = i;
                g_topscore[b * KTOP + pos] = __uint_as_float(u);
                pos++;
            }
        }
    }
}

// ---------------- fused head ----------------
__global__ __launch_bounds__(256, 1)
void head_kernel(const float* __restrict__ Wsec, const float* __restrict__ bsec,
                 const float* __restrict__ Wpred, const float* __restrict__ bpred,
                 const int* __restrict__ mask, float* __restrict__ out) {
    extern __shared__ float sm[];
    float* xs  = sm;                        // 256*68
    float* ws  = xs + 256 * XST;            // 256*128
    float* bc  = ws + 256 * 128;            // 128 (bsec + inj)
    float* wpc = bc + 128;                  // 128
    float* red = wpc + 128;                 // 64*16
    __shared__ int sS[64], sE[64];
    __shared__ float sMask[64], sScore[64];

    const int b   = blockIdx.y;
    const int k0  = blockIdx.x * 64;
    const int tid = threadIdx.x;
    const int tx  = tid & 15, ty = tid >> 4;

    if (tid < 64) {
        int n = g_topidx[b * KTOP + k0 + tid];
        int s = g_sarr[n], e = g_earr[n];
        sS[tid] = s; sE[tid] = e;
        sMask[tid] = (mask[b * Tt + s] != 0 && mask[b * Tt + e] != 0) ? 1.f : 0.f;
        float sc = g_topscore[b * KTOP + k0 + tid];
        sScore[tid] = isinf(sc) ? -1.f : sc;
    }
    __syncthreads();

    const float* Ab = g_A + b * Tt * Hh;
    const float* Eb = g_E + b * Tt * Hh;
    for (int r = 0; r < 64; r++)
        xs[tid * XST + r] = Ab[sS[r] * Hh + tid] + Eb[sE[r] * Hh + tid];

    float scacc[4] = {0.f, 0.f, 0.f, 0.f};

    #pragma unroll 1
    for (int jb = 0; jb < 2; jb++) {
        const int jbase = jb * 128;
        __syncthreads();
        #pragma unroll
        for (int idx = tid; idx < 8192; idx += 256) {
            int k = idx >> 5, c4 = idx & 31;
            ((float4*)ws)[idx] = ((const float4*)(Wsec + k * Hh + jbase))[c4];
        }
        if (tid < 128) {
            bc[tid]  = bsec[jbase + tid] + g_inj[b * Hh + jbase + tid];
            wpc[tid] = Wpred[jbase + tid];
        }
        __syncthreads();

        u64 acc[4][4] = {};
        const float* xp = xs + (ty << 2);
        const float* wl = ws + (tx << 2);
        const float* wh = wl + 64;
        #pragma unroll 4
        for (int k = 0; k < Hh; k++) {
            const float4 a = *(const float4*)(xp + k * XST);
            u64 w0, w1, w2, w3;
            lds_pair(w0, w1, wl + (k << 7));
            lds_pair(w2, w3, wh + (k << 7));
            u64 d0 = dup2(a.x), d1 = dup2(a.y), d2 = dup2(a.z), d3 = dup2(a.w);
            fma2(acc[0][0], d0, w0); fma2(acc[0][1], d0, w1);
            fma2(acc[0][2], d0, w2); fma2(acc[0][3], d0, w3);
            fma2(acc[1][0], d1, w0); fma2(acc[1][1], d1, w1);
            fma2(acc[1][2], d1, w2); fma2(acc[1][3], d1, w3);
            fma2(acc[2][0], d2, w0); fma2(acc[2][1], d2, w1);
            fma2(acc[2][2], d2, w2); fma2(acc[2][3], d2, w3);
            fma2(acc[3][0], d3, w0); fma2(acc[3][1], d3, w1);
            fma2(acc[3][2], d3, w2); fma2(acc[3][3], d3, w3);
        }
        #pragma unroll
        for (int i = 0; i < 4; i++) {
            #pragma unroll
            for (int p = 0; p < 4; p++) {
                float lo, hi;
                unpack2(lo, hi, acc[i][p]);
                int cb = (p < 2) ? ((tx << 2) + 2 * p) : (64 + (tx << 2) + 2 * (p - 2));
                float h0 = lo + bc[cb];
                if (h0 > 0.f) scacc[i] = fmaf(h0, wpc[cb], scacc[i]);
                float h1 = hi + bc[cb + 1];
                if (h1 > 0.f) scacc[i] = fmaf(h1, wpc[cb + 1], scacc[i]);
            }
        }
    }

    __syncthreads();
    #pragma unroll
    for (int i = 0; i < 4; i++) red[((ty << 2) + i) * 16 + tx] = scacc[i];
    __syncthreads();
    if (tid < 64) {
        float ssum = bpred[0] + sScore[tid];
        #pragma unroll
        for (int t = 0; t < 16; t++) ssum += red[tid * 16 + t];
        float p = 1.f / (1.f + expf(-ssum));
        out[b * KTOP + k0 + tid] = p * sMask[tid];
    }
}

// ---------------- launch ----------------
extern "C" void kernel_launch(void* const* d_in, const int* in_sizes, int n_in,
                              void* d_out, int out_size) {
    const float* inputs   = (const float*)d_in[0];
    const int*   in_mask  = (const int*)  d_in[1];
    const float* tie      = (const float*)d_in[2];
    const float* W_start  = (const float*)d_in[3];
    const float* b_start  = (const float*)d_in[4];
    const float* W_end    = (const float*)d_in[5];
    const float* b_end    = (const float*)d_in[6];
    const float* W_s1     = (const float*)d_in[7];
    const float* b_s1     = (const float*)d_in[8];
    const float* W_s2     = (const float*)d_in[9];
    const float* b_s2     = (const float*)d_in[10];
    const float* W_inj    = (const float*)d_in[11];
    const float* b_inj    = (const float*)d_in[12];
    const float* W_sec    = (const float*)d_in[13];
    const float* b_sec    = (const float*)d_in[14];
    const float* W_pred   = (const float*)d_in[15];
    const float* b_pred   = (const float*)d_in[16];
    float* out = (float*)d_out;

    cudaFuncSetAttribute(scorer_kernel, cudaFuncAttributeMaxDynamicSharedMemorySize, SMEM_BYTES);
    cudaFuncSetAttribute(head_kernel,   cudaFuncAttributeMaxDynamicSharedMemorySize, SMEM_BYTES);

    build_span_idx_kernel<<<(NSPANS + 255) / 256, 256>>>();
    proj_kernel<<<dim3(Hh / 64, (Bb * Tt) / 64, 2), 256>>>(inputs, W_start, b_start, W_end, b_end);
    inj_kernel<<<Bb, 256>>>(tie, W_inj, b_inj);
    scorer_kernel<<<dim3(NSPANS / 64, Bb), 256, SMEM_BYTES>>>(W_s1, b_s1, W_s2, b_s2);
    topk_kernel<<<Bb, 256>>>(in_mask);
    head_kernel<<<dim3(KTOP / 64, Bb), 256, SMEM_BYTES>>>(W_sec, b_sec, W_pred, b_pred, in_mask, out);
}

// round 3
// speedup vs baseline: 1.7718x; 1.2372x over previous
#include <cuda_runtime.h>
#include <math.h>

#define Bb      64
#define Tt      128
#define Dd      768
#define Hh      256
#define NSPANS  8256
#define KTOP    256
#define XST     68          // head/legacy xs stride
#define RST     132         // scorer xs row-stride (128 rows + pad)

typedef unsigned long long u64;

// ---------------- packed fp32x2 helpers (sm_103a FFMA2 path) ----------------
__device__ __forceinline__ u64 dup2(float a) {
    u64 r;
    asm("mov.b64 %0, {%1, %2};" : "=l"(r) : "f"(a), "f"(a));
    return r;
}
__device__ __forceinline__ void fma2(u64& acc, u64 a, u64 b) {
    asm("fma.rn.f32x2 %0, %1, %2, %0;" : "+l"(acc) : "l"(a), "l"(b));
}
__device__ __forceinline__ void unpack2(float& lo, float& hi, u64 v) {
    asm("mov.b64 {%0, %1}, %2;" : "=f"(lo), "=f"(hi) : "l"(v));
}
__device__ __forceinline__ void lds_pair(u64& x, u64& y, const float* p) {
    unsigned addr = (unsigned)__cvta_generic_to_shared(p);
    asm volatile("ld.shared.v2.u64 {%0, %1}, [%2];" : "=l"(x), "=l"(y) : "r"(addr));
}

// ---------------- device scratch ----------------
__device__ float g_A[Bb*Tt*Hh];
__device__ float g_E[Bb*Tt*Hh];
__device__ float g_scores[Bb*NSPANS];
__device__ float g_inj[Bb*Hh];
__device__ int   g_topidx[Bb*KTOP];
__device__ float g_topscore[Bb*KTOP];
__device__ int   g_sarr[NSPANS];
__device__ int   g_earr[NSPANS];

// ---------------- span index decode ----------------
__global__ void build_span_idx_kernel() {
    int n = blockIdx.x * blockDim.x + threadIdx.x;
    if (n >= NSPANS) return;
    int s = 0, off = 0;
    while (n >= off + (Tt - s)) { off += (Tt - s); s++; }
    g_sarr[n] = s;
    g_earr[n] = s + (n - off);
}

// ---------------- projections: X[8192,768]@W[768,256]+b, 128x64 tile, 8x4/thread ----------------
__global__ __launch_bounds__(256)
void proj_kernel(const float* __restrict__ X,
                 const float* __restrict__ Wst, const float* __restrict__ bst,
                 const float* __restrict__ Wen, const float* __restrict__ ben) {
    const float* W    = blockIdx.z ? Wen : Wst;
    const float* bias = blockIdx.z ? ben : bst;
    float*       Out  = blockIdx.z ? g_E : g_A;

    __shared__ float xs[32 * RST];      // [k][r], 128 rows
    __shared__ float wsm[32 * XST];     // [k][c], 64 cols

    const int row0 = blockIdx.y * 128;
    const int col0 = blockIdx.x * 64;
    const int tid  = threadIdx.x;
    const int tx   = tid & 15, ty = tid >> 4;

    u64 acc[8][2] = {};

    for (int k0 = 0; k0 < Dd; k0 += 32) {
        __syncthreads();
        #pragma unroll
        for (int idx = tid; idx < 128 * 32; idx += 256) {
            int r = idx >> 5, k = idx & 31;
            xs[k * RST + r] = X[(row0 + r) * Dd + k0 + k];
        }
        #pragma unroll
        for (int idx = tid; idx < 32 * 64; idx += 256) {
            int k = idx >> 6, cc = idx & 63;
            wsm[k * XST + cc] = W[(k0 + k) * Hh + col0 + cc];
        }
        __syncthreads();
        #pragma unroll 4
        for (int k = 0; k < 32; k++) {
            const float4 a0 = *(const float4*)(xs + k * RST + (ty << 3));
            const float4 a1 = *(const float4*)(xs + k * RST + (ty << 3) + 4);
            u64 w0, w1;
            lds_pair(w0, w1, wsm + k * XST + (tx << 2));
            u64 d0 = dup2(a0.x), d1 = dup2(a0.y), d2 = dup2(a0.z), d3 = dup2(a0.w);
            u64 d4 = dup2(a1.x), d5 = dup2(a1.y), d6 = dup2(a1.z), d7 = dup2(a1.w);
            fma2(acc[0][0], d0, w0); fma2(acc[0][1], d0, w1);
            fma2(acc[1][0], d1, w0); fma2(acc[1][1], d1, w1);
            fma2(acc[2][0], d2, w0); fma2(acc[2][1], d2, w1);
            fma2(acc[3][0], d3, w0); fma2(acc[3][1], d3, w1);
            fma2(acc[4][0], d4, w0); fma2(acc[4][1], d4, w1);
            fma2(acc[5][0], d5, w0); fma2(acc[5][1], d5, w1);
            fma2(acc[6][0], d6, w0); fma2(acc[6][1], d6, w1);
            fma2(acc[7][0], d7, w0); fma2(acc[7][1], d7, w1);
        }
    }

    #pragma unroll
    for (int i = 0; i < 8; i++) {
        int row = row0 + (ty << 3) + i;
        #pragma unroll
        for (int p = 0; p < 2; p++) {
            float lo, hi;
            unpack2(lo, hi, acc[i][p]);
            int col = col0 + (tx << 2) + 2 * p;
            Out[row * Hh + col]     = lo + bias[col];
            Out[row * Hh + col + 1] = hi + bias[col + 1];
        }
    }
}

// ---------------- injection projection ----------------
__global__ void inj_kernel(const float* __restrict__ tie,
                           const float* __restrict__ Winj, const float* __restrict__ binj) {
    int b = blockIdx.x;
    int j = threadIdx.x;
    __shared__ float t[128];
    if (j < 128) t[j] = tie[b * 128 + j];
    __syncthreads();
    float acc = binj[j];
    #pragma unroll 8
    for (int k = 0; k < 128; k++) acc = fmaf(t[k], Winj[k * Hh + j], acc);
    g_inj[b * Hh + j] = acc;
}

// ---------------- fused span scorer: 128 spans/CTA, 8x8 micro-tile ----------------
// smem: xs[256k][RST=132] + ws[128k][128c] + bs1c[128] + w2c[128] + red[128*16]
#define SC_SMEM_FLOATS (256*RST + 128*128 + 128 + 128 + 128*16)
static const int SC_SMEM_BYTES = SC_SMEM_FLOATS * 4;   // 209,920 B

__global__ __launch_bounds__(256, 1)
void scorer_kernel(const float* __restrict__ Ws1, const float* __restrict__ bs1,
                   const float* __restrict__ Ws2, const float* __restrict__ bs2) {
    extern __shared__ float sm[];
    float* xs   = sm;                        // 256*132
    float* ws   = xs + 256 * RST;            // 128*128 (k-chunk staged)
    float* bs1c = ws + 128 * 128;            // 128
    float* w2c  = bs1c + 128;                // 128
    float* red  = w2c + 128;                 // 128*16
    __shared__ int sS[128], sE[128];

    const int b   = blockIdx.y;
    const int n0  = blockIdx.x * 128;
    const int tid = threadIdx.x;
    const int tx  = tid & 15, ty = tid >> 4;

    if (tid < 128) {
        int n = n0 + tid;
        if (n > NSPANS - 1) n = NSPANS - 1;
        sS[tid] = g_sarr[n]; sE[tid] = g_earr[n];
    }
    __syncthreads();

    const float* Ab = g_A + b * Tt * Hh;
    const float* Eb = g_E + b * Tt * Hh;
    // xs[k=tid][r] = relu(A[s_r][k] + E[e_r][k])
    for (int r = 0; r < 128; r++) {
        float v = Ab[sS[r] * Hh + tid] + Eb[sE[r] * Hh + tid];
        xs[tid * RST + r] = v > 0.f ? v : 0.f;
    }

    float scacc[8] = {0.f, 0.f, 0.f, 0.f, 0.f, 0.f, 0.f, 0.f};

    #pragma unroll 1
    for (int jb = 0; jb < 2; jb++) {
        const int jbase = jb << 7;
        u64 acc[8][4] = {};

        #pragma unroll 1
        for (int kc = 0; kc < 2; kc++) {
            const int k0 = kc << 7;
            __syncthreads();
            // stage 128k x 128c weight chunk (float4)
            #pragma unroll
            for (int idx = tid; idx < 4096; idx += 256) {
                int kk = idx >> 5, c4 = idx & 31;
                ((float4*)ws)[idx] = ((const float4*)(Ws1 + (k0 + kk) * Hh + jbase))[c4];
            }
            if (kc == 0 && tid < 128) {
                bs1c[tid] = bs1[jbase + tid];
                w2c[tid]  = Ws2[jbase + tid];
            }
            __syncthreads();

            const float* xp = xs + k0 * RST + (ty << 3);
            const float* wp = ws + (tx << 3);
            #pragma unroll 2
            for (int k = 0; k < 128; k++) {
                const float4 a0 = *(const float4*)(xp + k * RST);
                const float4 a1 = *(const float4*)(xp + k * RST + 4);
                u64 w0, w1, w2, w3;
                lds_pair(w0, w1, wp + (k << 7));
                lds_pair(w2, w3, wp + (k << 7) + 4);
                u64 d0 = dup2(a0.x), d1 = dup2(a0.y), d2 = dup2(a0.z), d3 = dup2(a0.w);
                u64 d4 = dup2(a1.x), d5 = dup2(a1.y), d6 = dup2(a1.z), d7 = dup2(a1.w);
                fma2(acc[0][0], d0, w0); fma2(acc[0][1], d0, w1);
                fma2(acc[0][2], d0, w2); fma2(acc[0][3], d0, w3);
                fma2(acc[1][0], d1, w0); fma2(acc[1][1], d1, w1);
                fma2(acc[1][2], d1, w2); fma2(acc[1][3], d1, w3);
                fma2(acc[2][0], d2, w0); fma2(acc[2][1], d2, w1);
                fma2(acc[2][2], d2, w2); fma2(acc[2][3], d2, w3);
                fma2(acc[3][0], d3, w0); fma2(acc[3][1], d3, w1);
                fma2(acc[3][2], d3, w2); fma2(acc[3][3], d3, w3);
                fma2(acc[4][0], d4, w0); fma2(acc[4][1], d4, w1);
                fma2(acc[4][2], d4, w2); fma2(acc[4][3], d4, w3);
                fma2(acc[5][0], d5, w0); fma2(acc[5][1], d5, w1);
                fma2(acc[5][2], d5, w2); fma2(acc[5][3], d5, w3);
                fma2(acc[6][0], d6, w0); fma2(acc[6][1], d6, w1);
                fma2(acc[6][2], d6, w2); fma2(acc[6][3], d6, w3);
                fma2(acc[7][0], d7, w0); fma2(acc[7][1], d7, w1);
                fma2(acc[7][2], d7, w2); fma2(acc[7][3], d7, w3);
            }
        }

        // layer-2 epilogue for this j-stage
        #pragma unroll
        for (int i = 0; i < 8; i++) {
            #pragma unroll
            for (int p = 0; p < 4; p++) {
                float lo, hi;
                unpack2(lo, hi, acc[i][p]);
                int cb = (tx << 3) + 2 * p;
                float h0 = lo + bs1c[cb];
                if (h0 > 0.f) scacc[i] = fmaf(h0, w2c[cb], scacc[i]);
                float h1 = hi + bs1c[cb + 1];
                if (h1 > 0.f) scacc[i] = fmaf(h1, w2c[cb + 1], scacc[i]);
            }
        }
    }

    __syncthreads();
    #pragma unroll
    for (int i = 0; i < 8; i++) red[((ty << 3) + i) * 16 + tx] = scacc[i];
    __syncthreads();
    if (tid < 128 && n0 + tid < NSPANS) {
        float ssum = bs2[0];
        #pragma unroll
        for (int t = 0; t < 16; t++) ssum += red[tid * 16 + t];
        g_scores[b * NSPANS + n0 + tid] = ssum;
    }
}

// ---------------- per-batch radix top-k, parallel stable extraction ----------------
__global__ void topk_kernel(const int* __restrict__ mask) {
    const int b   = blockIdx.x;
    const int tid = threadIdx.x;
    __shared__ unsigned keys[NSPANS];
    __shared__ int hist[256];
    __shared__ unsigned sh_prefix;
    __shared__ int sh_kk;
    __shared__ int sgt[256], seqv[256];

    const int* mb = mask + b * Tt;
    for (int i = tid; i < NSPANS; i += 256) {
        int s = g_sarr[i], e = g_earr[i];
        float v = (mb[s] != 0 && mb[e] != 0) ? g_scores[b * NSPANS + i]
                                             : __int_as_float(0xff800000);
        unsigned u = __float_as_uint(v);
        keys[i] = (u & 0x80000000u) ? ~u : (u | 0x80000000u);
    }

    unsigned prefix = 0;
    int kk = KTOP;
    for (int level = 3; level >= 0; level--) {
        hist[tid] = 0;
        __syncthreads();
        const unsigned himask = (level == 3) ? 0u : (0xFFFFFFFFu << ((level + 1) * 8));
        for (int i = tid; i < NSPANS; i += 256) {
            unsigned kv = keys[i];
            if ((kv & himask) == (prefix & himask))
                atomicAdd(&hist[(kv >> (level * 8)) & 255], 1);
        }
        __syncthreads();
        if (tid == 0) {
            int cum = 0, chosen = 0, kknew = kk;
            for (int t = 255; t >= 0; t--) {
                int c = hist[t];
                if (cum + c >= kk) { chosen = t; kknew = kk - cum; break; }
                cum += c;
            }
            sh_prefix = prefix | ((unsigned)chosen << (level * 8));
            sh_kk = kknew;
        }
        __syncthreads();
        prefix = sh_prefix;
        kk = sh_kk;
        __syncthreads();
    }

    // parallel extraction: chunked counts + prefix + rank-preserving writes
    const unsigned Kstar = prefix;
    const int CH = (NSPANS + 255) / 256;   // 33
    int lo = tid * CH; if (lo > NSPANS) lo = NSPANS;
    int hi = lo + CH;  if (hi > NSPANS) hi = NSPANS;

    int cgt = 0, ceq = 0;
    for (int i = lo; i < hi; i++) {
        unsigned kv = keys[i];
        cgt += (kv > Kstar);
        ceq += (kv == Kstar);
    }
    sgt[tid] = cgt; seqv[tid] = ceq;
    __syncthreads();
    if (tid == 0) {       // exclusive prefix (serial, 256 elems — cheap)
        int ag = 0, ae = 0;
        for (int t = 0; t < 256; t++) {
            int g = sgt[t], e = seqv[t];
            sgt[t] = ag; seqv[t] = ae;
            ag += g; ae += e;
        }
    }
    __syncthreads();

    int gtb = sgt[tid], eqb = seqv[tid];
    for (int i = lo; i < hi; i++) {
        unsigned kv = keys[i];
        bool isgt = (kv > Kstar);
        bool iseq = (kv == Kstar);
        if (isgt || (iseq && eqb < kk)) {
            int eqt = eqb < kk ? eqb : kk;
            int pos = gtb + eqt;
            unsigned u = (kv & 0x80000000u) ? (kv & 0x7FFFFFFFu) : ~kv;
            g_topidx[b * KTOP + pos]   = i;
            g_topscore[b * KTOP + pos] = __uint_as_float(u);
        }
        gtb += isgt;
        eqb += iseq;
    }
}

// ---------------- fused head (as round 2) ----------------
#define HD_SMEM_FLOATS (256*XST + 256*128 + 128 + 128 + 64*16)
static const int HD_SMEM_BYTES = HD_SMEM_FLOATS * 4;  // 205,824 B

__global__ __launch_bounds__(256, 1)
void head_kernel(const float* __restrict__ Wsec, const float* __restrict__ bsec,
                 const float* __restrict__ Wpred, const float* __restrict__ bpred,
                 const int* __restrict__ mask, float* __restrict__ out) {
    extern __shared__ float sm[];
    float* xs  = sm;
    float* ws  = xs + 256 * XST;
    float* bc  = ws + 256 * 128;
    float* wpc = bc + 128;
    float* red = wpc + 128;
    __shared__ int sS[64], sE[64];
    __shared__ float sMask[64], sScore[64];

    const int b   = blockIdx.y;
    const int k0  = blockIdx.x * 64;
    const int tid = threadIdx.x;
    const int tx  = tid & 15, ty = tid >> 4;

    if (tid < 64) {
        int n = g_topidx[b * KTOP + k0 + tid];
        int s = g_sarr[n], e = g_earr[n];
        sS[tid] = s; sE[tid] = e;
        sMask[tid] = (mask[b * Tt + s] != 0 && mask[b * Tt + e] != 0) ? 1.f : 0.f;
        float sc = g_topscore[b * KTOP + k0 + tid];
        sScore[tid] = isinf(sc) ? -1.f : sc;
    }
    __syncthreads();

    const float* Ab = g_A + b * Tt * Hh;
    const float* Eb = g_E + b * Tt * Hh;
    for (int r = 0; r < 64; r++)
        xs[tid * XST + r] = Ab[sS[r] * Hh + tid] + Eb[sE[r] * Hh + tid];

    float scacc[4] = {0.f, 0.f, 0.f, 0.f};

    #pragma unroll 1
    for (int jb = 0; jb < 2; jb++) {
        const int jbase = jb * 128;
        __syncthreads();
        #pragma unroll
        for (int idx = tid; idx < 8192; idx += 256) {
            int k = idx >> 5, c4 = idx & 31;
            ((float4*)ws)[idx] = ((const float4*)(Wsec + k * Hh + jbase))[c4];
        }
        if (tid < 128) {
            bc[tid]  = bsec[jbase + tid] + g_inj[b * Hh + jbase + tid];
            wpc[tid] = Wpred[jbase + tid];
        }
        __syncthreads();

        u64 acc[4][4] = {};
        const float* xp = xs + (ty << 2);
        const float* wl = ws + (tx << 2);
        const float* wh = wl + 64;
        #pragma unroll 4
        for (int k = 0; k < Hh; k++) {
            const float4 a = *(const float4*)(xp + k * XST);
            u64 w0, w1, w2, w3;
            lds_pair(w0, w1, wl + (k << 7));
            lds_pair(w2, w3, wh + (k << 7));
            u64 d0 = dup2(a.x), d1 = dup2(a.y), d2 = dup2(a.z), d3 = dup2(a.w);
            fma2(acc[0][0], d0, w0); fma2(acc[0][1], d0, w1);
            fma2(acc[0][2], d0, w2); fma2(acc[0][3], d0, w3);
            fma2(acc[1][0], d1, w0); fma2(acc[1][1], d1, w1);
            fma2(acc[1][2], d1, w2); fma2(acc[1][3], d1, w3);
            fma2(acc[2][0], d2, w0); fma2(acc[2][1], d2, w1);
            fma2(acc[2][2], d2, w2); fma2(acc[2][3], d2, w3);
            fma2(acc[3][0], d3, w0); fma2(acc[3][1], d3, w1);
            fma2(acc[3][2], d3, w2); fma2(acc[3][3], d3, w3);
        }
        #pragma unroll
        for (int i = 0; i < 4; i++) {
            #pragma unroll
            for (int p = 0; p < 4; p++) {
                float lo, hi;
                unpack2(lo, hi, acc[i][p]);
                int cb = (p < 2) ? ((tx << 2) + 2 * p) : (64 + (tx << 2) + 2 * (p - 2));
                float h0 = lo + bc[cb];
                if (h0 > 0.f) scacc[i] = fmaf(h0, wpc[cb], scacc[i]);
                float h1 = hi + bc[cb + 1];
                if (h1 > 0.f) scacc[i] = fmaf(h1, wpc[cb + 1], scacc[i]);
            }
        }
    }

    __syncthreads();
    #pragma unroll
    for (int i = 0; i < 4; i++) red[((ty << 2) + i) * 16 + tx] = scacc[i];
    __syncthreads();
    if (tid < 64) {
        float ssum = bpred[0] + sScore[tid];
        #pragma unroll
        for (int t = 0; t < 16; t++) ssum += red[tid * 16 + t];
        float p = 1.f / (1.f + expf(-ssum));
        out[b * KTOP + k0 + tid] = p * sMask[tid];
    }
}

// ---------------- launch ----------------
extern "C" void kernel_launch(void* const* d_in, const int* in_sizes, int n_in,
                              void* d_out, int out_size) {
    const float* inputs   = (const float*)d_in[0];
    const int*   in_mask  = (const int*)  d_in[1];
    const float* tie      = (const float*)d_in[2];
    const float* W_start  = (const float*)d_in[3];
    const float* b_start  = (const float*)d_in[4];
    const float* W_end    = (const float*)d_in[5];
    const float* b_end    = (const float*)d_in[6];
    const float* W_s1     = (const float*)d_in[7];
    const float* b_s1     = (const float*)d_in[8];
    const float* W_s2     = (const float*)d_in[9];
    const float* b_s2     = (const float*)d_in[10];
    const float* W_inj    = (const float*)d_in[11];
    const float* b_inj    = (const float*)d_in[12];
    const float* W_sec    = (const float*)d_in[13];
    const float* b_sec    = (const float*)d_in[14];
    const float* W_pred   = (const float*)d_in[15];
    const float* b_pred   = (const float*)d_in[16];
    float* out = (float*)d_out;

    cudaFuncSetAttribute(scorer_kernel, cudaFuncAttributeMaxDynamicSharedMemorySize, SC_SMEM_BYTES);
    cudaFuncSetAttribute(head_kernel,   cudaFuncAttributeMaxDynamicSharedMemorySize, HD_SMEM_BYTES);

    build_span_idx_kernel<<<(NSPANS + 255) / 256, 256>>>();
    proj_kernel<<<dim3(Hh / 64, (Bb * Tt) / 128, 2), 256>>>(inputs, W_start, b_start, W_end, b_end);
    inj_kernel<<<Bb, 256>>>(tie, W_inj, b_inj);
    scorer_kernel<<<dim3((NSPANS + 127) / 128, Bb), 256, SC_SMEM_BYTES>>>(W_s1, b_s1, W_s2, b_s2);
    topk_kernel<<<Bb, 256>>>(in_mask);
    head_kernel<<<dim3(KTOP / 64, Bb), 256, HD_SMEM_BYTES>>>(W_sec, b_sec, W_pred, b_pred, in_mask, out);
}